// round 2
// baseline (speedup 1.0000x reference)
#include <cuda_runtime.h>
#include <math.h>

#define FULLMASK 0xffffffffu

// ---------------- scratch (device globals; no allocations allowed) ----------
__device__ int      g_idx[4 * 4096 * 32];     // ball-query indices   (2 MB)
__device__ float    g_abs[4 * 4096 * 96];     // absolute sin-emb     (6 MB)
__device__ unsigned g_pooled[4 * 256];        // order-keyed max pool

// ---------------- small helpers --------------------------------------------
__device__ __forceinline__ unsigned long long pk2(float a, float b) {
    unsigned long long r;
    asm("mov.b64 %0, {%1, %2};" : "=l"(r) : "f"(a), "f"(b));
    return r;
}
__device__ __forceinline__ void upk2(unsigned long long v, float& a, float& b) {
    asm("mov.b64 {%0, %1}, %2;" : "=f"(a), "=f"(b) : "l"(v));
}
// packed fp32x2 FMA: d = a*b + d   (2 FMAs / instruction on sm_103a)
__device__ __forceinline__ void ffma2(unsigned long long& d, unsigned long long a,
                                      unsigned long long b) {
    asm("fma.rn.f32x2 %0, %1, %2, %0;" : "+l"(d) : "l"(a), "l"(b));
}
// order-preserving float<->uint map for atomicMax
__device__ __forceinline__ unsigned fkey(float f) {
    int i = __float_as_int(f);
    return (i >= 0) ? ((unsigned)i | 0x80000000u) : ~(unsigned)i;
}
__device__ __forceinline__ float funkey(unsigned u) {
    int i = (u & 0x80000000u) ? (int)(u & 0x7fffffffu) : (int)(~u);
    return __int_as_float(i);
}
__device__ __forceinline__ float gelu_exact(float x) {
    return 0.5f * x * (1.0f + erff(x * 0.70710678118654752f));
}

// ---------------- kernel 0: init pooled max to -inf key ---------------------
__global__ void k_init() {
    int t = blockIdx.x * blockDim.x + threadIdx.x;
    if (t < 1024) g_pooled[t] = 0x007FFFFFu;   // fkey(-inf)
}

// ---------------- kernel 1: ball query + absolute position embedding --------
// grid (N/8, B), 256 threads. One warp per query point, xyz staged in SMEM.
__global__ __launch_bounds__(256) void k_ball(const float* __restrict__ xyz) {
    __shared__ float sx[4096], sy[4096], sz[4096];
    const int b = blockIdx.y;
    const float* base = xyz + (size_t)b * 4096 * 3;
    for (int i = threadIdx.x; i < 4096; i += 256) {
        float3 v = *(const float3*)(base + 3 * i);
        sx[i] = v.x; sy[i] = v.y; sz[i] = v.z;
    }
    __syncthreads();

    const int lane = threadIdx.x & 31, warp = threadIdx.x >> 5;
    const int n = blockIdx.x * 8 + warp;
    const float qx = sx[n], qy = sy[n], qz = sz[n];
    const int p = (b << 12) + n;

    int cnt = 0, fm = n;
    for (int c = 0; c < 128; c++) {
        int m = c * 32 + lane;
        float dx = sx[m] - qx, dy = sy[m] - qy, dz = sz[m] - qz;
        // match JAX rounding: mul/add, NO fma contraction
        float sq = __fadd_rn(__fadd_rn(__fmul_rn(dx, dx), __fmul_rn(dy, dy)),
                             __fmul_rn(dz, dz));
        bool in = (sq <= 0.0256f);                 // exclude only sq > r^2
        unsigned mask = __ballot_sync(FULLMASK, in);
        if (mask) {
            if (cnt == 0) fm = c * 32 + (__ffs(mask) - 1);  // first in-ball index
            if (in) {
                int pos = cnt + __popc(mask & ((1u << lane) - 1u));
                if (pos < 32) g_idx[p * 32 + pos] = m;
            }
            cnt += __popc(mask);
            if (cnt >= 32) break;
        }
    }
    for (int k = cnt + lane; k < 32; k += 32) g_idx[p * 32 + k] = fm;  // pad

    // absolute sin-emb: dim 96 = 3 axes * (16 sin + 16 cos)
    int jj = lane & 15;
    float fr = expf((-logf(10000.0f) * (float)jj) / 15.0f);
    float co[3] = {qx, qy, qz};
#pragma unroll
    for (int a = 0; a < 3; a++) {
        float ang = co[a] * fr;
        g_abs[(size_t)p * 96 + a * 32 + lane] = (lane >= 16) ? cosf(ang) : sinf(ang);
    }
}

// ---------------- kernel 2: fused MLP(187->256->256) + joint max pool -------
// 64 rows (= 2 query points x K=32) per block, 256 threads.
// thread microtile: 8 rows x 8 cols; each warp owns 8 whole rows -> LN via shfl.
#define LDX 192
#define SMEM_MLP ((64 * LDX + 64 * 256 + 32 * 256) * 4 + 64 * 4)

__global__ __launch_bounds__(256) void k_mlp(
    const float* __restrict__ xyz, const float* __restrict__ pf,
    const float* __restrict__ w1, const float* __restrict__ b1,
    const float* __restrict__ g1, const float* __restrict__ be1,
    const float* __restrict__ w2, const float* __restrict__ b2,
    const float* __restrict__ g2, const float* __restrict__ be2) {
    extern __shared__ float sm[];
    float* Xs = sm;                      // 64 x 192  (187 + zero pad)
    float* Hs = Xs + 64 * LDX;           // 64 x 256
    float* Wb = Hs + 64 * 256;           // 32 x 256 weight chunk (reused as red)
    int* sm_m = (int*)(Wb + 32 * 256);   // 64 neighbor ids

    const int t = threadIdx.x, lane = t & 31, warp = t >> 5;
    const int p0 = blockIdx.x * 2;
    const int b = p0 >> 12;

    // ---- build input rows X[i][0..186] -------------------------------------
    if (t < 64) {
        int p = p0 + (t >> 5);
        int n = p & 4095;
        int m = g_idx[p * 32 + (t & 31)];
        sm_m[t] = m;
        const float* xm = xyz + ((size_t)(b << 12) + m) * 3;
        const float* xn = xyz + ((size_t)(b << 12) + n) * 3;
        float* Xr = Xs + t * LDX;
        Xr[64] = xm[0] - xn[0];
        Xr[65] = xm[1] - xn[1];
        Xr[66] = xm[2] - xn[2];
        Xr[187] = 0.f; Xr[188] = 0.f; Xr[189] = 0.f; Xr[190] = 0.f; Xr[191] = 0.f;
    }
    for (int e = t; e < 64 * 96; e += 256) {           // absolute emb (shared per point)
        int i = e / 96, j = e - 96 * i;
        int p = p0 + (i >> 5);
        Xs[i * LDX + 91 + j] = g_abs[(size_t)p * 96 + j];
    }
    __syncthreads();
    for (int e = t; e < 64 * 64; e += 256) {           // grouped features
        int i = e >> 6, j = e & 63;
        Xs[i * LDX + j] = pf[(((size_t)(b << 12)) + sm_m[i]) * 64 + j];
    }
    for (int e = t; e < 64 * 24; e += 256) {           // relative sin-emb (24)
        int i = e / 24, j = e - 24 * i;
        int a = j >> 3, jj = j & 7;
        float rel = Xs[i * LDX + 64 + a];
        float fr = expf((-logf(10000.0f) * (float)(jj & 3)) / 3.0f);
        float ang = rel * fr;
        Xs[i * LDX + 67 + j] = (jj < 4) ? sinf(ang) : cosf(ang);
    }

    const int c0 = lane * 8;
    unsigned long long acc[8][4];

    // =================== layer 1: X[64x187(192)] @ W1 -> acc =================
    {
        unsigned long long bias[4];
#pragma unroll
        for (int q = 0; q < 4; q++)
            bias[q] = pk2(__ldg(&b1[c0 + 2 * q]), __ldg(&b1[c0 + 2 * q + 1]));
#pragma unroll
        for (int r = 0; r < 8; r++)
#pragma unroll
            for (int q = 0; q < 4; q++) acc[r][q] = bias[q];

        for (int kb = 0; kb < 192; kb += 32) {
            __syncthreads();
            for (int v = t; v < 2048; v += 256) {
                int kk = kb + (v >> 6);
                float4 val = (kk < 187) ? __ldg(&((const float4*)w1)[kk * 64 + (v & 63)])
                                        : make_float4(0.f, 0.f, 0.f, 0.f);
                ((float4*)Wb)[v] = val;
            }
            __syncthreads();
            const float* Sc = Xs + warp * 8 * LDX + kb;
#pragma unroll 2
            for (int kl = 0; kl < 32; kl += 4) {
                float4 xq[8];
#pragma unroll
                for (int r = 0; r < 8; r++)
                    xq[r] = *(const float4*)(Sc + r * LDX + kl);
#pragma unroll
                for (int s = 0; s < 4; s++) {
                    ulonglong2 wa = *(const ulonglong2*)(Wb + (kl + s) * 256 + c0);
                    ulonglong2 wc = *(const ulonglong2*)(Wb + (kl + s) * 256 + c0 + 4);
#pragma unroll
                    for (int r = 0; r < 8; r++) {
                        float xv = (s == 0) ? xq[r].x : (s == 1) ? xq[r].y
                                  : (s == 2) ? xq[r].z : xq[r].w;
                        unsigned long long x2 = pk2(xv, xv);
                        ffma2(acc[r][0], x2, wa.x);
                        ffma2(acc[r][1], x2, wa.y);
                        ffma2(acc[r][2], x2, wc.x);
                        ffma2(acc[r][3], x2, wc.y);
                    }
                }
            }
        }
    }

    // ---- LN1 + exact GELU -> Hs --------------------------------------------
    {
        float gg[8], bb[8];
#pragma unroll
        for (int j = 0; j < 8; j++) { gg[j] = __ldg(&g1[c0 + j]); bb[j] = __ldg(&be1[c0 + j]); }
#pragma unroll
        for (int r = 0; r < 8; r++) {
            float v[8];
            upk2(acc[r][0], v[0], v[1]); upk2(acc[r][1], v[2], v[3]);
            upk2(acc[r][2], v[4], v[5]); upk2(acc[r][3], v[6], v[7]);
            float s = 0.f;
#pragma unroll
            for (int j = 0; j < 8; j++) s += v[j];
#pragma unroll
            for (int o = 16; o; o >>= 1) s += __shfl_xor_sync(FULLMASK, s, o);
            float mu = s * (1.0f / 256.0f);
            float d[8]; float ss = 0.f;
#pragma unroll
            for (int j = 0; j < 8; j++) { d[j] = v[j] - mu; ss += d[j] * d[j]; }
#pragma unroll
            for (int o = 16; o; o >>= 1) ss += __shfl_xor_sync(FULLMASK, ss, o);
            float inv = rsqrtf(ss * (1.0f / 256.0f) + 1e-5f);
            float* Hr = Hs + (warp * 8 + r) * 256 + c0;
#pragma unroll
            for (int j = 0; j < 8; j++) {
                float h = d[j] * inv * gg[j] + bb[j];
                Hr[j] = gelu_exact(h);
            }
        }
    }

    // =================== layer 2: H[64x256] @ W2 -> acc ======================
    {
        unsigned long long bias[4];
#pragma unroll
        for (int q = 0; q < 4; q++)
            bias[q] = pk2(__ldg(&b2[c0 + 2 * q]), __ldg(&b2[c0 + 2 * q + 1]));
#pragma unroll
        for (int r = 0; r < 8; r++)
#pragma unroll
            for (int q = 0; q < 4; q++) acc[r][q] = bias[q];

        for (int kb = 0; kb < 256; kb += 32) {
            __syncthreads();
            for (int v = t; v < 2048; v += 256) {
                int kk = kb + (v >> 6);
                ((float4*)Wb)[v] = __ldg(&((const float4*)w2)[kk * 64 + (v & 63)]);
            }
            __syncthreads();
            const float* Sc = Hs + warp * 8 * 256 + kb;
#pragma unroll 2
            for (int kl = 0; kl < 32; kl += 4) {
                float4 xq[8];
#pragma unroll
                for (int r = 0; r < 8; r++)
                    xq[r] = *(const float4*)(Sc + r * 256 + kl);
#pragma unroll
                for (int s = 0; s < 4; s++) {
                    ulonglong2 wa = *(const ulonglong2*)(Wb + (kl + s) * 256 + c0);
                    ulonglong2 wc = *(const ulonglong2*)(Wb + (kl + s) * 256 + c0 + 4);
#pragma unroll
                    for (int r = 0; r < 8; r++) {
                        float xv = (s == 0) ? xq[r].x : (s == 1) ? xq[r].y
                                  : (s == 2) ? xq[r].z : xq[r].w;
                        unsigned long long x2 = pk2(xv, xv);
                        ffma2(acc[r][0], x2, wa.x);
                        ffma2(acc[r][1], x2, wa.y);
                        ffma2(acc[r][2], x2, wc.x);
                        ffma2(acc[r][3], x2, wc.y);
                    }
                }
            }
        }
    }

    // ---- LN2 + per-thread max over its 8 rows -------------------------------
    float mcol[8];
#pragma unroll
    for (int j = 0; j < 8; j++) mcol[j] = -INFINITY;
    {
        float gg[8], bb[8];
#pragma unroll
        for (int j = 0; j < 8; j++) { gg[j] = __ldg(&g2[c0 + j]); bb[j] = __ldg(&be2[c0 + j]); }
#pragma unroll
        for (int r = 0; r < 8; r++) {
            float v[8];
            upk2(acc[r][0], v[0], v[1]); upk2(acc[r][1], v[2], v[3]);
            upk2(acc[r][2], v[4], v[5]); upk2(acc[r][3], v[6], v[7]);
            float s = 0.f;
#pragma unroll
            for (int j = 0; j < 8; j++) s += v[j];
#pragma unroll
            for (int o = 16; o; o >>= 1) s += __shfl_xor_sync(FULLMASK, s, o);
            float mu = s * (1.0f / 256.0f);
            float d[8]; float ss = 0.f;
#pragma unroll
            for (int j = 0; j < 8; j++) { d[j] = v[j] - mu; ss += d[j] * d[j]; }
#pragma unroll
            for (int o = 16; o; o >>= 1) ss += __shfl_xor_sync(FULLMASK, ss, o);
            float inv = rsqrtf(ss * (1.0f / 256.0f) + 1e-5f);
#pragma unroll
            for (int j = 0; j < 8; j++) {
                float y = d[j] * inv * gg[j] + bb[j];
                mcol[j] = fmaxf(mcol[j], y);
            }
        }
    }

    // ---- block max (reuse Wb) then global atomic max ------------------------
    __syncthreads();
    float* red = Wb;   // 8 x 256
#pragma unroll
    for (int j = 0; j < 8; j++) red[warp * 256 + c0 + j] = mcol[j];
    __syncthreads();
    {
        int c = t;
        float mm = red[c];
#pragma unroll
        for (int w = 1; w < 8; w++) mm = fmaxf(mm, red[w * 256 + c]);
        atomicMax(&g_pooled[(b << 8) + c], fkey(mm));
    }
}

// ---------------- kernel 3: final 4-row MLP ---------------------------------
__device__ __forceinline__ float bsum256(float v, float* sred) {
#pragma unroll
    for (int o = 16; o; o >>= 1) v += __shfl_xor_sync(FULLMASK, v, o);
    if ((threadIdx.x & 31) == 0) sred[threadIdx.x >> 5] = v;
    __syncthreads();
    float s = 0.f;
#pragma unroll
    for (int w = 0; w < 8; w++) s += sred[w];
    __syncthreads();
    return s;
}

__global__ __launch_bounds__(256) void k_final(
    const float* __restrict__ pw1, const float* __restrict__ pb1,
    const float* __restrict__ pg1, const float* __restrict__ pbe1,
    const float* __restrict__ pw2, const float* __restrict__ pb2,
    const float* __restrict__ pg2, const float* __restrict__ pbe2,
    float* __restrict__ out) {
    __shared__ float xin[4][256];
    __shared__ float hh[4][256];
    __shared__ float sred[8];
    const int t = threadIdx.x;
    for (int i = t; i < 1024; i += 256) ((float*)xin)[i] = funkey(g_pooled[i]);
    __syncthreads();

    float acc[4];
#pragma unroll
    for (int b = 0; b < 4; b++) acc[b] = pb1[t];
    for (int k = 0; k < 256; k++) {
        float w = pw1[k * 256 + t];
#pragma unroll
        for (int b = 0; b < 4; b++) acc[b] = fmaf(xin[b][k], w, acc[b]);
    }
#pragma unroll
    for (int b = 0; b < 4; b++) hh[b][t] = acc[b];
    __syncthreads();
    for (int b = 0; b < 4; b++) {
        float val = hh[b][t];
        float mu = bsum256(val, sred) * (1.0f / 256.0f);
        float d = val - mu;
        float var = bsum256(d * d, sred) * (1.0f / 256.0f);
        float y = d * rsqrtf(var + 1e-5f) * pg1[t] + pbe1[t];
        xin[b][t] = gelu_exact(y);
    }
    __syncthreads();
#pragma unroll
    for (int b = 0; b < 4; b++) acc[b] = pb2[t];
    for (int k = 0; k < 256; k++) {
        float w = pw2[k * 256 + t];
#pragma unroll
        for (int b = 0; b < 4; b++) acc[b] = fmaf(xin[b][k], w, acc[b]);
    }
#pragma unroll
    for (int b = 0; b < 4; b++) hh[b][t] = acc[b];
    __syncthreads();
    for (int b = 0; b < 4; b++) {
        float val = hh[b][t];
        float mu = bsum256(val, sred) * (1.0f / 256.0f);
        float d = val - mu;
        float var = bsum256(d * d, sred) * (1.0f / 256.0f);
        out[b * 256 + t] = d * rsqrtf(var + 1e-5f) * pg2[t] + pbe2[t];
    }
}

// ---------------- launcher ---------------------------------------------------
extern "C" void kernel_launch(void* const* d_in, const int* in_sizes, int n_in,
                              void* d_out, int out_size) {
    const float* xyz  = (const float*)d_in[0];
    const float* pf   = (const float*)d_in[1];
    const float* w1   = (const float*)d_in[2];
    const float* b1   = (const float*)d_in[3];
    const float* g1   = (const float*)d_in[4];
    const float* be1  = (const float*)d_in[5];
    const float* w2   = (const float*)d_in[6];
    const float* b2   = (const float*)d_in[7];
    const float* g2   = (const float*)d_in[8];
    const float* be2  = (const float*)d_in[9];
    const float* pw1  = (const float*)d_in[10];
    const float* pb1  = (const float*)d_in[11];
    const float* pg1  = (const float*)d_in[12];
    const float* pbe1 = (const float*)d_in[13];
    const float* pw2  = (const float*)d_in[14];
    const float* pb2  = (const float*)d_in[15];
    const float* pg2  = (const float*)d_in[16];
    const float* pbe2 = (const float*)d_in[17];
    float* out = (float*)d_out;

    cudaFuncSetAttribute(k_mlp, cudaFuncAttributeMaxDynamicSharedMemorySize, SMEM_MLP);

    k_init<<<4, 256>>>();
    k_ball<<<dim3(512, 4), 256>>>(xyz);
    k_mlp<<<8192, 256, SMEM_MLP>>>(xyz, pf, w1, b1, g1, be1, w2, b2, g2, be2);
    k_final<<<1, 256>>>(pw1, pb1, pg1, pbe1, pw2, pb2, pg2, pbe2, out);
}

// round 4
// speedup vs baseline: 2.7360x; 2.7360x over previous
#include <cuda_runtime.h>
#include <cstdint>
#include <math.h>

#define FULLMASK 0xffffffffu
#define LDX2 264                         // row stride (floats): 264 % 32 == 8 -> conflict-free

// ==================== device scratch (no allocations allowed) ===============
__device__ int      g_idx[4 * 4096 * 32];
__device__ float    g_abs[4 * 4096 * 96];
__device__ unsigned g_pooled[4 * 256];
__device__ float4   g_w1t[6 * 2048];     // 6 chunks x 32KB fragment-linear images
__device__ float4   g_w2t[8 * 2048];     // 8 chunks x 32KB
__device__ float    g_fp1[16 * 1024], g_fp2[16 * 1024], g_ft[1024];

// ==================== helpers ===============================================
__device__ __forceinline__ uint32_t smem_u32(const void* p) {
    uint32_t a;
    asm("{ .reg .u64 t; cvta.to.shared.u64 t, %1; cvt.u32.u64 %0, t; }" : "=r"(a) : "l"(p));
    return a;
}
__device__ __forceinline__ uint32_t tf32bits(float x) {
    uint32_t u;
    asm("cvt.rna.tf32.f32 %0, %1;" : "=r"(u) : "f"(x));
    return u;
}
__device__ __forceinline__ unsigned fkey(float f) {
    int i = __float_as_int(f);
    return (i >= 0) ? ((unsigned)i | 0x80000000u) : ~(unsigned)i;
}
__device__ __forceinline__ float funkey(unsigned u) {
    int i = (u & 0x80000000u) ? (int)(u & 0x7fffffffu) : (int)(~u);
    return __int_as_float(i);
}
__device__ __forceinline__ float gelu_exact(float x) {
    return 0.5f * x * (1.0f + erff(x * 0.70710678118654752f));
}
// m16n8k8 tf32 warp MMA (family-portable sm_80+ path -> HMMA on tensor pipe)
__device__ __forceinline__ void mma8(float4& d, const uint32_t* a, uint2 b) {
    asm volatile("mma.sync.aligned.m16n8k8.row.col.f32.tf32.tf32.f32 "
                 "{%0,%1,%2,%3}, {%4,%5,%6,%7}, {%8,%9}, {%0,%1,%2,%3};"
                 : "+f"(d.x), "+f"(d.y), "+f"(d.z), "+f"(d.w)
                 : "r"(a[0]), "r"(a[1]), "r"(a[2]), "r"(a[3]), "r"(b.x), "r"(b.y));
}
__device__ __forceinline__ void cp16(uint32_t sdst, const void* gsrc) {
    asm volatile("cp.async.cg.shared.global [%0], [%1], 16;" :: "r"(sdst), "l"(gsrc));
}

// ==================== kernel 0: init pooled =================================
__global__ void k_init() {
    int t = blockIdx.x * blockDim.x + threadIdx.x;
    if (t < 1024) g_pooled[t] = 0x007FFFFFu;   // fkey(-inf)
}

// ==================== kernel P: fragment-linear weight images ===============
// Image layout: uint2[((chunk*4 + ks)*32 + nt)*32 + lane] = {W[k0][n], W[k0+4][n]}
// with k0 = chunk*32 + ks*8 + lane%4, n = nt*8 + lane/4  (tf32-rounded)
__global__ __launch_bounds__(256) void k_prep(const float* __restrict__ w1,
                                              const float* __restrict__ w2) {
    int id = blockIdx.x * 256 + threadIdx.x;
    if (id < 24576) {                      // layer 1: 6 chunks
        int lane = id & 31, nt = (id >> 5) & 31, ks = (id >> 10) & 3, c = id >> 12;
        int k0 = c * 32 + ks * 8 + (lane & 3);
        int n = nt * 8 + (lane >> 2);
        float v0 = (k0 < 187) ? w1[k0 * 256 + n] : 0.f;
        float v1 = (k0 + 4 < 187) ? w1[(k0 + 4) * 256 + n] : 0.f;
        uint2 r; r.x = tf32bits(v0); r.y = tf32bits(v1);
        ((uint2*)g_w1t)[id] = r;
    } else if (id < 24576 + 32768) {       // layer 2: 8 chunks
        int e = id - 24576;
        int lane = e & 31, nt = (e >> 5) & 31, ks = (e >> 10) & 3, c = e >> 12;
        int k0 = c * 32 + ks * 8 + (lane & 3);
        int n = nt * 8 + (lane >> 2);
        uint2 r;
        r.x = tf32bits(w2[k0 * 256 + n]);
        r.y = tf32bits(w2[(k0 + 4) * 256 + n]);
        ((uint2*)g_w2t)[e] = r;
    }
}

// ==================== kernel 1: ball query + absolute emb (validated R1) ====
__global__ __launch_bounds__(256) void k_ball(const float* __restrict__ xyz) {
    __shared__ float sx[4096], sy[4096], sz[4096];
    const int b = blockIdx.y;
    const float* base = xyz + (size_t)b * 4096 * 3;
    for (int i = threadIdx.x; i < 4096; i += 256) {
        float3 v = *(const float3*)(base + 3 * i);
        sx[i] = v.x; sy[i] = v.y; sz[i] = v.z;
    }
    __syncthreads();
    const int lane = threadIdx.x & 31, warp = threadIdx.x >> 5;
    const int n = blockIdx.x * 8 + warp;
    const float qx = sx[n], qy = sy[n], qz = sz[n];
    const int p = (b << 12) + n;
    int cnt = 0, fm = n;
    for (int c = 0; c < 128; c++) {
        int m = c * 32 + lane;
        float dx = sx[m] - qx, dy = sy[m] - qy, dz = sz[m] - qz;
        float sq = __fadd_rn(__fadd_rn(__fmul_rn(dx, dx), __fmul_rn(dy, dy)), __fmul_rn(dz, dz));
        bool in = (sq <= 0.0256f);
        unsigned mask = __ballot_sync(FULLMASK, in);
        if (mask) {
            if (cnt == 0) fm = c * 32 + (__ffs(mask) - 1);
            if (in) {
                int pos = cnt + __popc(mask & ((1u << lane) - 1u));
                if (pos < 32) g_idx[p * 32 + pos] = m;
            }
            cnt += __popc(mask);
            if (cnt >= 32) break;
        }
    }
    for (int k = cnt + lane; k < 32; k += 32) g_idx[p * 32 + k] = fm;
    int jj = lane & 15;
    float fr = expf((-logf(10000.0f) * (float)jj) / 15.0f);
    float co[3] = {qx, qy, qz};
#pragma unroll
    for (int a = 0; a < 3; a++) {
        float ang = co[a] * fr;
        g_abs[(size_t)p * 96 + a * 32 + lane] = (lane >= 16) ? cosf(ang) : sinf(ang);
    }
}

// ==================== kernel 2: mma.sync tf32 fused MLP + joint max =========
// CTA: 128 rows (4 points x K=32) x 256 cols; 8 warps in 2(M) x 4(N) grid.
#define SMEM_DYN (128 * LDX2 * 4 + 2 * 32768)

// double-buffered K-chunk GEMM: acc += X[128 x 32*nchunks] @ Wimg
__device__ __forceinline__ void gemm_loop(const uint32_t* __restrict__ Xu,
                                          float* W0, float* W1,
                                          const float4* __restrict__ gw, int nchunks,
                                          int wr, int wc, int lane, int t,
                                          float4 acc[4][8]) {
    const int gid = lane >> 2, tid4 = lane & 3;
    uint32_t w0a = smem_u32(W0), w1a = smem_u32(W1);
    {
        const float4* src = gw;
#pragma unroll
        for (int u = 0; u < 8; u++) cp16(w0a + (t + u * 256) * 16, src + t + u * 256);
    }
    asm volatile("cp.async.commit_group;" ::: "memory");
    for (int i = 0; i < nchunks; i++) {
        const uint2* Bbuf = (const uint2*)((i & 1) ? W1 : W0);
        if (i + 1 < nchunks) {
            uint32_t dst = (i & 1) ? w0a : w1a;
            const float4* src = gw + (i + 1) * 2048;
#pragma unroll
            for (int u = 0; u < 8; u++) cp16(dst + (t + u * 256) * 16, src + t + u * 256);
            asm volatile("cp.async.commit_group;" ::: "memory");
            asm volatile("cp.async.wait_group 1;" ::: "memory");
        } else {
            asm volatile("cp.async.wait_group 0;" ::: "memory");
        }
        __syncthreads();
#pragma unroll
        for (int ks = 0; ks < 4; ks++) {
            uint32_t a[4][4];
            const int colk = i * 32 + ks * 8 + tid4;
#pragma unroll
            for (int tile = 0; tile < 4; tile++) {
                int row = wr * 64 + tile * 16 + gid;
                a[tile][0] = Xu[row * LDX2 + colk];
                a[tile][1] = Xu[(row + 8) * LDX2 + colk];
                a[tile][2] = Xu[row * LDX2 + colk + 4];
                a[tile][3] = Xu[(row + 8) * LDX2 + colk + 4];
            }
            uint2 b[8];
            const uint2* Bp = Bbuf + ((ks * 32 + wc * 8) * 32 + lane);
#pragma unroll
            for (int nt = 0; nt < 8; nt++) b[nt] = Bp[nt * 32];
#pragma unroll
            for (int tile = 0; tile < 4; tile++)
#pragma unroll
                for (int nt = 0; nt < 8; nt++) mma8(acc[tile][nt], a[tile], b[nt]);
        }
        __syncthreads();
    }
}

__global__ __launch_bounds__(256, 1) void k_mlp(
    const float* __restrict__ xyz, const float* __restrict__ pf,
    const float* __restrict__ b1, const float* __restrict__ g1, const float* __restrict__ be1,
    const float* __restrict__ b2, const float* __restrict__ g2, const float* __restrict__ be2) {
    extern __shared__ float dsm[];
    __shared__ float s_b[256], s_g[256], s_be[256];
    __shared__ float s_sum[128][4], s_sq[128][4];
    __shared__ float s_mu[128], s_inv[128];
    __shared__ float s_cmax[2][256];

    float* Xs = dsm;                         // 128 x 264 f32 (X, later H)
    uint32_t* Xu = (uint32_t*)dsm;
    float* W0 = dsm + 128 * LDX2;
    float* W1 = W0 + 8192;

    const int t = threadIdx.x, lane = t & 31, warp = t >> 5;
    const int gid = lane >> 2, tid4 = lane & 3;
    const int wr = warp >> 2, wc = warp & 3;
    const int p0 = blockIdx.x * 4, bB = p0 >> 12;

    s_b[t] = b1[t]; s_g[t] = g1[t]; s_be[t] = be1[t];

    // ---- build X[128 x 192] (tf32 bits, row-major) ---------------------------
    {
        const int r = t >> 1, h = t & 1;
        const int p = p0 + (r >> 5);
        const int n = p & 4095;
        const int m = g_idx[(p << 5) + (r & 31)];
        const float* xm = xyz + ((size_t)(bB << 12) + m) * 3;
        const float* xn = xyz + ((size_t)(bB << 12) + n) * 3;
        float rel[3] = {xm[0] - xn[0], xm[1] - xn[1], xm[2] - xn[2]};
        uint32_t* Xr = Xu + r * LDX2;
        const float4* pfr = (const float4*)(pf + ((size_t)(bB << 12) + m) * 64) + h * 8;
#pragma unroll
        for (int u = 0; u < 8; u++) {
            float4 f = __ldg(&pfr[u]);
            int c = h * 32 + u * 4;
            Xr[c + 0] = tf32bits(f.x); Xr[c + 1] = tf32bits(f.y);
            Xr[c + 2] = tf32bits(f.z); Xr[c + 3] = tf32bits(f.w);
        }
        if (h == 0) {
#pragma unroll
            for (int a = 0; a < 3; a++) Xr[64 + a] = tf32bits(rel[a]);
        } else {
#pragma unroll
            for (int c = 187; c < 192; c++) Xr[c] = 0u;
        }
#pragma unroll
        for (int u = 0; u < 12; u++) {        // relative sin-emb (24)
            int j = h * 12 + u;
            int a = j >> 3, w8 = j & 7;
            float fr = expf((-logf(10000.0f) * (float)(w8 & 3)) / 3.0f);
            float ang = rel[a] * fr;
            float v = (w8 < 4) ? sinf(ang) : cosf(ang);
            Xr[67 + j] = tf32bits(v);
        }
        const float* ga = g_abs + (size_t)p * 96 + h * 48;   // absolute emb (96)
#pragma unroll
        for (int u = 0; u < 48; u++) Xr[91 + h * 48 + u] = tf32bits(ga[u]);
    }
    __syncthreads();

    // ---- layer 1 GEMM ---------------------------------------------------------
    float4 acc[4][8];
#pragma unroll
    for (int nt = 0; nt < 8; nt++) {
        int c0 = wc * 64 + nt * 8 + 2 * tid4;
        float bx = s_b[c0], by = s_b[c0 + 1];
#pragma unroll
        for (int tile = 0; tile < 4; tile++) acc[tile][nt] = make_float4(bx, by, bx, by);
    }
    gemm_loop(Xu, W0, W1, g_w1t, 6, wr, wc, lane, t, acc);

    // ---- epilogue 1: LN stats -> mu/inv -> GELU -> H (in place) ---------------
#pragma unroll
    for (int tile = 0; tile < 4; tile++) {
        float s0 = 0.f, q0 = 0.f, s1 = 0.f, q1 = 0.f;
#pragma unroll
        for (int nt = 0; nt < 8; nt++) {
            float4 c = acc[tile][nt];
            s0 += c.x + c.y; q0 += c.x * c.x + c.y * c.y;
            s1 += c.z + c.w; q1 += c.z * c.z + c.w * c.w;
        }
        s0 += __shfl_xor_sync(FULLMASK, s0, 1); s0 += __shfl_xor_sync(FULLMASK, s0, 2);
        q0 += __shfl_xor_sync(FULLMASK, q0, 1); q0 += __shfl_xor_sync(FULLMASK, q0, 2);
        s1 += __shfl_xor_sync(FULLMASK, s1, 1); s1 += __shfl_xor_sync(FULLMASK, s1, 2);
        q1 += __shfl_xor_sync(FULLMASK, q1, 1); q1 += __shfl_xor_sync(FULLMASK, q1, 2);
        if (tid4 == 0) {
            int r0 = wr * 64 + tile * 16 + gid;
            s_sum[r0][wc] = s0; s_sq[r0][wc] = q0;
            s_sum[r0 + 8][wc] = s1; s_sq[r0 + 8][wc] = q1;
        }
    }
    __syncthreads();
    if (t < 128) {
        float s = s_sum[t][0] + s_sum[t][1] + s_sum[t][2] + s_sum[t][3];
        float q = s_sq[t][0] + s_sq[t][1] + s_sq[t][2] + s_sq[t][3];
        float mu = s * (1.0f / 256.0f);
        s_mu[t] = mu;
        s_inv[t] = rsqrtf(fmaxf(q * (1.0f / 256.0f) - mu * mu, 0.f) + 1e-5f);
    }
    __syncthreads();
#pragma unroll
    for (int tile = 0; tile < 4; tile++) {
        int r0 = wr * 64 + tile * 16 + gid;
        float mu0 = s_mu[r0], inv0 = s_inv[r0], mu1 = s_mu[r0 + 8], inv1 = s_inv[r0 + 8];
#pragma unroll
        for (int nt = 0; nt < 8; nt++) {
            int c0 = wc * 64 + nt * 8 + 2 * tid4;
            float gg0 = s_g[c0], gg1 = s_g[c0 + 1], bb0 = s_be[c0], bb1 = s_be[c0 + 1];
            float4 c = acc[tile][nt];
            uint2 lo, hi;
            lo.x = tf32bits(gelu_exact((c.x - mu0) * inv0 * gg0 + bb0));
            lo.y = tf32bits(gelu_exact((c.y - mu0) * inv0 * gg1 + bb1));
            hi.x = tf32bits(gelu_exact((c.z - mu1) * inv1 * gg0 + bb0));
            hi.y = tf32bits(gelu_exact((c.w - mu1) * inv1 * gg1 + bb1));
            *(uint2*)(Xu + r0 * LDX2 + c0) = lo;
            *(uint2*)(Xu + (r0 + 8) * LDX2 + c0) = hi;
        }
    }
    __syncthreads();
    s_b[t] = b2[t]; s_g[t] = g2[t]; s_be[t] = be2[t];
    __syncthreads();

    // ---- layer 2 GEMM (A = H, K = 256) -----------------------------------------
#pragma unroll
    for (int nt = 0; nt < 8; nt++) {
        int c0 = wc * 64 + nt * 8 + 2 * tid4;
        float bx = s_b[c0], by = s_b[c0 + 1];
#pragma unroll
        for (int tile = 0; tile < 4; tile++) acc[tile][nt] = make_float4(bx, by, bx, by);
    }
    gemm_loop(Xu, W0, W1, g_w2t, 8, wr, wc, lane, t, acc);

    // ---- epilogue 2: LN stats then LN + joint column max ------------------------
#pragma unroll
    for (int tile = 0; tile < 4; tile++) {
        float s0 = 0.f, q0 = 0.f, s1 = 0.f, q1 = 0.f;
#pragma unroll
        for (int nt = 0; nt < 8; nt++) {
            float4 c = acc[tile][nt];
            s0 += c.x + c.y; q0 += c.x * c.x + c.y * c.y;
            s1 += c.z + c.w; q1 += c.z * c.z + c.w * c.w;
        }
        s0 += __shfl_xor_sync(FULLMASK, s0, 1); s0 += __shfl_xor_sync(FULLMASK, s0, 2);
        q0 += __shfl_xor_sync(FULLMASK, q0, 1); q0 += __shfl_xor_sync(FULLMASK, q0, 2);
        s1 += __shfl_xor_sync(FULLMASK, s1, 1); s1 += __shfl_xor_sync(FULLMASK, s1, 2);
        q1 += __shfl_xor_sync(FULLMASK, q1, 1); q1 += __shfl_xor_sync(FULLMASK, q1, 2);
        if (tid4 == 0) {
            int r0 = wr * 64 + tile * 16 + gid;
            s_sum[r0][wc] = s0; s_sq[r0][wc] = q0;
            s_sum[r0 + 8][wc] = s1; s_sq[r0 + 8][wc] = q1;
        }
    }
    __syncthreads();
    if (t < 128) {
        float s = s_sum[t][0] + s_sum[t][1] + s_sum[t][2] + s_sum[t][3];
        float q = s_sq[t][0] + s_sq[t][1] + s_sq[t][2] + s_sq[t][3];
        float mu = s * (1.0f / 256.0f);
        s_mu[t] = mu;
        s_inv[t] = rsqrtf(fmaxf(q * (1.0f / 256.0f) - mu * mu, 0.f) + 1e-5f);
    }
    __syncthreads();
    {
        float m0[8], m1[8];
#pragma unroll
        for (int nt = 0; nt < 8; nt++) { m0[nt] = -INFINITY; m1[nt] = -INFINITY; }
#pragma unroll
        for (int tile = 0; tile < 4; tile++) {
            int r0 = wr * 64 + tile * 16 + gid;
            float mu0 = s_mu[r0], inv0 = s_inv[r0], mu1 = s_mu[r0 + 8], inv1 = s_inv[r0 + 8];
#pragma unroll
            for (int nt = 0; nt < 8; nt++) {
                int c0 = wc * 64 + nt * 8 + 2 * tid4;
                float gg0 = s_g[c0], gg1 = s_g[c0 + 1], bb0 = s_be[c0], bb1 = s_be[c0 + 1];
                float4 c = acc[tile][nt];
                float y00 = (c.x - mu0) * inv0 * gg0 + bb0;
                float y01 = (c.y - mu0) * inv0 * gg1 + bb1;
                float y10 = (c.z - mu1) * inv1 * gg0 + bb0;
                float y11 = (c.w - mu1) * inv1 * gg1 + bb1;
                m0[nt] = fmaxf(m0[nt], fmaxf(y00, y10));
                m1[nt] = fmaxf(m1[nt], fmaxf(y01, y11));
            }
        }
#pragma unroll
        for (int nt = 0; nt < 8; nt++) {
#pragma unroll
            for (int o = 4; o <= 16; o <<= 1) {
                m0[nt] = fmaxf(m0[nt], __shfl_xor_sync(FULLMASK, m0[nt], o));
                m1[nt] = fmaxf(m1[nt], __shfl_xor_sync(FULLMASK, m1[nt], o));
            }
            if (gid == 0) {
                int c0 = wc * 64 + nt * 8 + 2 * tid4;
                s_cmax[wr][c0] = m0[nt];
                s_cmax[wr][c0 + 1] = m1[nt];
            }
        }
    }
    __syncthreads();
    {
        float mm = fmaxf(s_cmax[0][t], s_cmax[1][t]);
        atomicMax(&g_pooled[(bB << 8) + t], fkey(mm));
    }
}

// ==================== final 4-row MLP (k-sliced, 4 tiny kernels) =============
__device__ __forceinline__ float bsum256(float v, float* sred) {
#pragma unroll
    for (int o = 16; o; o >>= 1) v += __shfl_xor_sync(FULLMASK, v, o);
    if ((threadIdx.x & 31) == 0) sred[threadIdx.x >> 5] = v;
    __syncthreads();
    float s = 0.f;
#pragma unroll
    for (int w = 0; w < 8; w++) s += sred[w];
    __syncthreads();
    return s;
}

__global__ __launch_bounds__(256) void k_fg(const float* __restrict__ w, int stage) {
    __shared__ float xin[4][256];
    int j = blockIdx.x, t = threadIdx.x;
    if (stage == 0)
        for (int i = t; i < 1024; i += 256) ((float*)xin)[i] = funkey(g_pooled[i]);
    else
        for (int i = t; i < 1024; i += 256) ((float*)xin)[i] = g_ft[i];
    __syncthreads();
    float a0 = 0.f, a1 = 0.f, a2 = 0.f, a3 = 0.f;
#pragma unroll
    for (int kk = 0; kk < 16; kk++) {
        float wv = __ldg(&w[(j * 16 + kk) * 256 + t]);
        a0 = fmaf(xin[0][j * 16 + kk], wv, a0);
        a1 = fmaf(xin[1][j * 16 + kk], wv, a1);
        a2 = fmaf(xin[2][j * 16 + kk], wv, a2);
        a3 = fmaf(xin[3][j * 16 + kk], wv, a3);
    }
    float* dst = stage ? g_fp2 : g_fp1;
    dst[(j * 4 + 0) * 256 + t] = a0;
    dst[(j * 4 + 1) * 256 + t] = a1;
    dst[(j * 4 + 2) * 256 + t] = a2;
    dst[(j * 4 + 3) * 256 + t] = a3;
}

__global__ __launch_bounds__(256) void k_fr(const float* __restrict__ bias,
                                            const float* __restrict__ gam,
                                            const float* __restrict__ bet,
                                            int stage, float* __restrict__ out) {
    __shared__ float sred[8];
    int t = threadIdx.x;
    const float* src = stage ? g_fp2 : g_fp1;
    for (int b = 0; b < 4; b++) {
        float y = bias[t];
#pragma unroll
        for (int j = 0; j < 16; j++) y += src[(j * 4 + b) * 256 + t];
        float mu = bsum256(y, sred) * (1.0f / 256.0f);
        float d = y - mu;
        float var = bsum256(d * d, sred) * (1.0f / 256.0f);
        float z = d * rsqrtf(var + 1e-5f) * gam[t] + bet[t];
        if (stage == 0) g_ft[b * 256 + t] = gelu_exact(z);
        else out[b * 256 + t] = z;
    }
}

// ==================== launcher ===============================================
extern "C" void kernel_launch(void* const* d_in, const int* in_sizes, int n_in,
                              void* d_out, int out_size) {
    const float* xyz  = (const float*)d_in[0];
    const float* pf   = (const float*)d_in[1];
    const float* w1   = (const float*)d_in[2];
    const float* b1   = (const float*)d_in[3];
    const float* g1   = (const float*)d_in[4];
    const float* be1  = (const float*)d_in[5];
    const float* w2   = (const float*)d_in[6];
    const float* b2   = (const float*)d_in[7];
    const float* g2   = (const float*)d_in[8];
    const float* be2  = (const float*)d_in[9];
    const float* pw1  = (const float*)d_in[10];
    const float* pb1  = (const float*)d_in[11];
    const float* pg1  = (const float*)d_in[12];
    const float* pbe1 = (const float*)d_in[13];
    const float* pw2  = (const float*)d_in[14];
    const float* pb2  = (const float*)d_in[15];
    const float* pg2  = (const float*)d_in[16];
    const float* pbe2 = (const float*)d_in[17];
    float* out = (float*)d_out;

    static int attr_done = 0;
    if (!attr_done) {
        cudaFuncSetAttribute(k_mlp, cudaFuncAttributeMaxDynamicSharedMemorySize, SMEM_DYN);
        attr_done = 1;
    }

    k_init<<<4, 256>>>();
    k_prep<<<224, 256>>>(w1, w2);
    k_ball<<<dim3(512, 4), 256>>>(xyz);
    k_mlp<<<4096, 256, SMEM_DYN>>>(xyz, pf, b1, g1, be1, b2, g2, be2);
    k_fg<<<16, 256>>>(pw1, 0);
    k_fr<<<1, 256>>>(pb1, pg1, pbe1, 0, out);
    k_fg<<<16, 256>>>(pw2, 1);
    k_fr<<<1, 256>>>(pb2, pg2, pbe2, 1, out);
}

// round 5
// speedup vs baseline: 3.5963x; 1.3144x over previous
#include <cuda_runtime.h>
#include <cstdint>
#include <math.h>

#define FULLMASK 0xffffffffu
#define LDX2 264                         // row stride (floats): 264 % 32 == 8 -> conflict-free

// ==================== device scratch (no allocations allowed) ===============
__device__ int      g_idx[4 * 4096 * 32];
__device__ float    g_abs[4 * 4096 * 96];
__device__ unsigned g_pooled[4 * 256];
__device__ float4   g_w1t[6 * 2048];     // 6 chunks x 32KB fragment-linear images
__device__ float4   g_w2t[8 * 2048];     // 8 chunks x 32KB
__device__ float    g_fp1[16 * 1024], g_fp2[16 * 1024], g_ft[1024];

// ==================== helpers ===============================================
__device__ __forceinline__ uint32_t smem_u32(const void* p) {
    uint32_t a;
    asm("{ .reg .u64 t; cvta.to.shared.u64 t, %1; cvt.u32.u64 %0, t; }" : "=r"(a) : "l"(p));
    return a;
}
__device__ __forceinline__ uint32_t tf32bits(float x) {
    uint32_t u;
    asm("cvt.rna.tf32.f32 %0, %1;" : "=r"(u) : "f"(x));
    return u;
}
__device__ __forceinline__ unsigned fkey(float f) {
    int i = __float_as_int(f);
    return (i >= 0) ? ((unsigned)i | 0x80000000u) : ~(unsigned)i;
}
__device__ __forceinline__ float funkey(unsigned u) {
    int i = (u & 0x80000000u) ? (int)(u & 0x7fffffffu) : (int)(~u);
    return __int_as_float(i);
}
__device__ __forceinline__ float gelu_exact(float x) {
    return 0.5f * x * (1.0f + erff(x * 0.70710678118654752f));
}
// m16n8k8 tf32 warp MMA (family-portable sm_80+ path -> tensor pipe)
__device__ __forceinline__ void mma8(float4& d, const uint32_t* a, uint2 b) {
    asm volatile("mma.sync.aligned.m16n8k8.row.col.f32.tf32.tf32.f32 "
                 "{%0,%1,%2,%3}, {%4,%5,%6,%7}, {%8,%9}, {%0,%1,%2,%3};"
                 : "+f"(d.x), "+f"(d.y), "+f"(d.z), "+f"(d.w)
                 : "r"(a[0]), "r"(a[1]), "r"(a[2]), "r"(a[3]), "r"(b.x), "r"(b.y));
}
__device__ __forceinline__ void cp16(uint32_t sdst, const void* gsrc) {
    asm volatile("cp.async.cg.shared.global [%0], [%1], 16;" :: "r"(sdst), "l"(gsrc));
}

// ==================== kernel 0: init pooled =================================
__global__ void k_init() {
    int t = blockIdx.x * blockDim.x + threadIdx.x;
    if (t < 1024) g_pooled[t] = 0x007FFFFFu;   // fkey(-inf)
}

// ==================== kernel P: fragment-linear weight images ===============
// uint2[((chunk*4 + ks)*32 + nt)*32 + lane] = {W[k0][n], W[k0+4][n]}
// k0 = chunk*32 + ks*8 + lane%4, n = nt*8 + lane/4  (tf32-rounded)
__global__ __launch_bounds__(256) void k_prep(const float* __restrict__ w1,
                                              const float* __restrict__ w2) {
    int id = blockIdx.x * 256 + threadIdx.x;
    if (id < 24576) {                      // layer 1: 6 chunks
        int lane = id & 31, nt = (id >> 5) & 31, ks = (id >> 10) & 3, c = id >> 12;
        int k0 = c * 32 + ks * 8 + (lane & 3);
        int n = nt * 8 + (lane >> 2);
        float v0 = (k0 < 187) ? w1[k0 * 256 + n] : 0.f;
        float v1 = (k0 + 4 < 187) ? w1[(k0 + 4) * 256 + n] : 0.f;
        uint2 r; r.x = tf32bits(v0); r.y = tf32bits(v1);
        ((uint2*)g_w1t)[id] = r;
    } else if (id < 24576 + 32768) {       // layer 2: 8 chunks
        int e = id - 24576;
        int lane = e & 31, nt = (e >> 5) & 31, ks = (e >> 10) & 3, c = e >> 12;
        int k0 = c * 32 + ks * 8 + (lane & 3);
        int n = nt * 8 + (lane >> 2);
        uint2 r;
        r.x = tf32bits(w2[k0 * 256 + n]);
        r.y = tf32bits(w2[(k0 + 4) * 256 + n]);
        ((uint2*)g_w2t)[e] = r;
    }
}

// ==================== kernel 1: ball query + absolute emb (validated) =======
__global__ __launch_bounds__(256) void k_ball(const float* __restrict__ xyz) {
    __shared__ float sx[4096], sy[4096], sz[4096];
    const int b = blockIdx.y;
    const float* base = xyz + (size_t)b * 4096 * 3;
    for (int i = threadIdx.x; i < 4096; i += 256) {
        float3 v = *(const float3*)(base + 3 * i);
        sx[i] = v.x; sy[i] = v.y; sz[i] = v.z;
    }
    __syncthreads();
    const int lane = threadIdx.x & 31, warp = threadIdx.x >> 5;
    const int n = blockIdx.x * 8 + warp;
    const float qx = sx[n], qy = sy[n], qz = sz[n];
    const int p = (b << 12) + n;
    int cnt = 0, fm = n;
    for (int c = 0; c < 128; c++) {
        int m = c * 32 + lane;
        float dx = sx[m] - qx, dy = sy[m] - qy, dz = sz[m] - qz;
        float sq = __fadd_rn(__fadd_rn(__fmul_rn(dx, dx), __fmul_rn(dy, dy)), __fmul_rn(dz, dz));
        bool in = (sq <= 0.0256f);
        unsigned mask = __ballot_sync(FULLMASK, in);
        if (mask) {
            if (cnt == 0) fm = c * 32 + (__ffs(mask) - 1);
            if (in) {
                int pos = cnt + __popc(mask & ((1u << lane) - 1u));
                if (pos < 32) g_idx[p * 32 + pos] = m;
            }
            cnt += __popc(mask);
            if (cnt >= 32) break;
        }
    }
    for (int k = cnt + lane; k < 32; k += 32) g_idx[p * 32 + k] = fm;
    int jj = lane & 15;
    float fr = expf((-logf(10000.0f) * (float)jj) / 15.0f);
    float co[3] = {qx, qy, qz};
#pragma unroll
    for (int a = 0; a < 3; a++) {
        float ang = co[a] * fr;
        g_abs[(size_t)p * 96 + a * 32 + lane] = (lane >= 16) ? cosf(ang) : sinf(ang);
    }
}

// ==================== kernel 2: mma.sync tf32 fused MLP + joint max =========
// CTA: 128 rows x 256 cols; 512 threads, 16 warps in 4(M) x 4(N) grid.
// Warp tile: 32 rows x 64 cols -> 64 accum floats/thread.
#define SMEM_DYN (128 * LDX2 * 4 + 2 * 32768)

__device__ __forceinline__ void gemm_loop(const uint32_t* __restrict__ Xu,
                                          float* W0, float* W1,
                                          const float4* __restrict__ gw, int nchunks,
                                          int wr, int wc, int lane, int t,
                                          float4 acc[2][8]) {
    const int gid = lane >> 2, tid4 = lane & 3;
    uint32_t w0a = smem_u32(W0), w1a = smem_u32(W1);
    {
        const float4* src = gw;
#pragma unroll
        for (int u = 0; u < 4; u++) cp16(w0a + (t + u * 512) * 16, src + t + u * 512);
    }
    asm volatile("cp.async.commit_group;" ::: "memory");
    for (int i = 0; i < nchunks; i++) {
        asm volatile("cp.async.wait_group 0;" ::: "memory");
        __syncthreads();
        if (i + 1 < nchunks) {                 // prefetch next chunk (overlaps compute)
            uint32_t dst = (i & 1) ? w0a : w1a;
            const float4* src = gw + (i + 1) * 2048;
#pragma unroll
            for (int u = 0; u < 4; u++) cp16(dst + (t + u * 512) * 16, src + t + u * 512);
            asm volatile("cp.async.commit_group;" ::: "memory");
        }
        const uint2* Bbuf = (const uint2*)((i & 1) ? W1 : W0);
#pragma unroll
        for (int ks = 0; ks < 4; ks++) {
            uint32_t a[2][4];
            const int colk = i * 32 + ks * 8 + tid4;
#pragma unroll
            for (int tile = 0; tile < 2; tile++) {
                int row = wr * 32 + tile * 16 + gid;
                a[tile][0] = Xu[row * LDX2 + colk];
                a[tile][1] = Xu[(row + 8) * LDX2 + colk];
                a[tile][2] = Xu[row * LDX2 + colk + 4];
                a[tile][3] = Xu[(row + 8) * LDX2 + colk + 4];
            }
            uint2 b[8];
            const uint2* Bp = Bbuf + ((ks * 32 + wc * 8) * 32 + lane);
#pragma unroll
            for (int nt = 0; nt < 8; nt++) b[nt] = Bp[nt * 32];
#pragma unroll
            for (int tile = 0; tile < 2; tile++)
#pragma unroll
                for (int nt = 0; nt < 8; nt++) mma8(acc[tile][nt], a[tile], b[nt]);
        }
    }
    __syncthreads();
}

__global__ __launch_bounds__(512, 1) void k_mlp(
    const float* __restrict__ xyz, const float* __restrict__ pf,
    const float* __restrict__ b1, const float* __restrict__ g1, const float* __restrict__ be1,
    const float* __restrict__ b2, const float* __restrict__ g2, const float* __restrict__ be2) {
    extern __shared__ float dsm[];
    __shared__ float s_b[256], s_g[256], s_be[256];
    __shared__ float s_sum[128][4], s_sq[128][4];
    __shared__ float s_mu[128], s_inv[128];
    __shared__ float s_cmax[4][256];

    uint32_t* Xu = (uint32_t*)dsm;           // 128 x 264 (X, later H)
    float* W0 = dsm + 128 * LDX2;
    float* W1 = W0 + 8192;

    const int t = threadIdx.x, lane = t & 31, warp = t >> 5;
    const int gid = lane >> 2, tid4 = lane & 3;
    const int wr = warp >> 2, wc = warp & 3;
    const int p0 = blockIdx.x * 4, bB = p0 >> 12;

    if (t < 256) { s_b[t] = b1[t]; s_g[t] = g1[t]; s_be[t] = be1[t]; }

    // ---- build X[128 x 192] (tf32 bits, row-major), 4 threads per row --------
    {
        const int r = t >> 2, h = t & 3;
        const int p = p0 + (r >> 5);
        const int n = p & 4095;
        const int m = g_idx[(p << 5) + (r & 31)];
        const float* xm = xyz + ((size_t)(bB << 12) + m) * 3;
        const float* xn = xyz + ((size_t)(bB << 12) + n) * 3;
        float rel[3] = {xm[0] - xn[0], xm[1] - xn[1], xm[2] - xn[2]};
        uint32_t* Xr = Xu + r * LDX2;
        const float4* pfr = (const float4*)(pf + ((size_t)(bB << 12) + m) * 64) + h * 4;
#pragma unroll
        for (int u = 0; u < 4; u++) {           // features: 16 cols each
            float4 f = __ldg(&pfr[u]);
            int c = h * 16 + u * 4;
            Xr[c + 0] = tf32bits(f.x); Xr[c + 1] = tf32bits(f.y);
            Xr[c + 2] = tf32bits(f.z); Xr[c + 3] = tf32bits(f.w);
        }
        if (h == 0) {
#pragma unroll
            for (int a = 0; a < 3; a++) Xr[64 + a] = tf32bits(rel[a]);
        } else if (h == 3) {
#pragma unroll
            for (int c = 187; c < 192; c++) Xr[c] = 0u;
        }
#pragma unroll
        for (int u = 0; u < 6; u++) {           // relative sin-emb: 6 each
            int j = h * 6 + u;
            int a = j >> 3, w8 = j & 7;
            float fr = expf((-logf(10000.0f) * (float)(w8 & 3)) / 3.0f);
            float ang = rel[a] * fr;
            float v = (w8 < 4) ? sinf(ang) : cosf(ang);
            Xr[67 + j] = tf32bits(v);
        }
        const float* ga = g_abs + (size_t)p * 96 + h * 24;   // absolute emb: 24 each
#pragma unroll
        for (int u = 0; u < 24; u++) Xr[91 + h * 24 + u] = tf32bits(ga[u]);
    }
    __syncthreads();

    // ---- layer 1 GEMM ---------------------------------------------------------
    float4 acc[2][8];
#pragma unroll
    for (int nt = 0; nt < 8; nt++) {
        int c0 = wc * 64 + nt * 8 + 2 * tid4;
        float bx = s_b[c0], by = s_b[c0 + 1];
#pragma unroll
        for (int tile = 0; tile < 2; tile++) acc[tile][nt] = make_float4(bx, by, bx, by);
    }
    gemm_loop(Xu, W0, W1, g_w1t, 6, wr, wc, lane, t, acc);

    // ---- epilogue 1: LN stats -> GELU -> H (in place) --------------------------
#pragma unroll
    for (int tile = 0; tile < 2; tile++) {
        float s0 = 0.f, q0 = 0.f, s1 = 0.f, q1 = 0.f;
#pragma unroll
        for (int nt = 0; nt < 8; nt++) {
            float4 c = acc[tile][nt];
            s0 += c.x + c.y; q0 += c.x * c.x + c.y * c.y;
            s1 += c.z + c.w; q1 += c.z * c.z + c.w * c.w;
        }
        s0 += __shfl_xor_sync(FULLMASK, s0, 1); s0 += __shfl_xor_sync(FULLMASK, s0, 2);
        q0 += __shfl_xor_sync(FULLMASK, q0, 1); q0 += __shfl_xor_sync(FULLMASK, q0, 2);
        s1 += __shfl_xor_sync(FULLMASK, s1, 1); s1 += __shfl_xor_sync(FULLMASK, s1, 2);
        q1 += __shfl_xor_sync(FULLMASK, q1, 1); q1 += __shfl_xor_sync(FULLMASK, q1, 2);
        if (tid4 == 0) {
            int r0 = wr * 32 + tile * 16 + gid;
            s_sum[r0][wc] = s0; s_sq[r0][wc] = q0;
            s_sum[r0 + 8][wc] = s1; s_sq[r0 + 8][wc] = q1;
        }
    }
    __syncthreads();
    if (t < 128) {
        float s = s_sum[t][0] + s_sum[t][1] + s_sum[t][2] + s_sum[t][3];
        float q = s_sq[t][0] + s_sq[t][1] + s_sq[t][2] + s_sq[t][3];
        float mu = s * (1.0f / 256.0f);
        s_mu[t] = mu;
        s_inv[t] = rsqrtf(fmaxf(q * (1.0f / 256.0f) - mu * mu, 0.f) + 1e-5f);
    }
    __syncthreads();
#pragma unroll
    for (int tile = 0; tile < 2; tile++) {
        int r0 = wr * 32 + tile * 16 + gid;
        float mu0 = s_mu[r0], inv0 = s_inv[r0], mu1 = s_mu[r0 + 8], inv1 = s_inv[r0 + 8];
#pragma unroll
        for (int nt = 0; nt < 8; nt++) {
            int c0 = wc * 64 + nt * 8 + 2 * tid4;
            float gg0 = s_g[c0], gg1 = s_g[c0 + 1], bb0 = s_be[c0], bb1 = s_be[c0 + 1];
            float4 c = acc[tile][nt];
            uint2 lo, hi;
            lo.x = tf32bits(gelu_exact((c.x - mu0) * inv0 * gg0 + bb0));
            lo.y = tf32bits(gelu_exact((c.y - mu0) * inv0 * gg1 + bb1));
            hi.x = tf32bits(gelu_exact((c.z - mu1) * inv1 * gg0 + bb0));
            hi.y = tf32bits(gelu_exact((c.w - mu1) * inv1 * gg1 + bb1));
            *(uint2*)(Xu + r0 * LDX2 + c0) = lo;
            *(uint2*)(Xu + (r0 + 8) * LDX2 + c0) = hi;
        }
    }
    __syncthreads();
    if (t < 256) { s_b[t] = b2[t]; s_g[t] = g2[t]; s_be[t] = be2[t]; }
    __syncthreads();

    // ---- layer 2 GEMM (A = H, K = 256) -----------------------------------------
#pragma unroll
    for (int nt = 0; nt < 8; nt++) {
        int c0 = wc * 64 + nt * 8 + 2 * tid4;
        float bx = s_b[c0], by = s_b[c0 + 1];
#pragma unroll
        for (int tile = 0; tile < 2; tile++) acc[tile][nt] = make_float4(bx, by, bx, by);
    }
    gemm_loop(Xu, W0, W1, g_w2t, 8, wr, wc, lane, t, acc);

    // ---- epilogue 2: LN stats then LN + joint column max ------------------------
#pragma unroll
    for (int tile = 0; tile < 2; tile++) {
        float s0 = 0.f, q0 = 0.f, s1 = 0.f, q1 = 0.f;
#pragma unroll
        for (int nt = 0; nt < 8; nt++) {
            float4 c = acc[tile][nt];
            s0 += c.x + c.y; q0 += c.x * c.x + c.y * c.y;
            s1 += c.z + c.w; q1 += c.z * c.z + c.w * c.w;
        }
        s0 += __shfl_xor_sync(FULLMASK, s0, 1); s0 += __shfl_xor_sync(FULLMASK, s0, 2);
        q0 += __shfl_xor_sync(FULLMASK, q0, 1); q0 += __shfl_xor_sync(FULLMASK, q0, 2);
        s1 += __shfl_xor_sync(FULLMASK, s1, 1); s1 += __shfl_xor_sync(FULLMASK, s1, 2);
        q1 += __shfl_xor_sync(FULLMASK, q1, 1); q1 += __shfl_xor_sync(FULLMASK, q1, 2);
        if (tid4 == 0) {
            int r0 = wr * 32 + tile * 16 + gid;
            s_sum[r0][wc] = s0; s_sq[r0][wc] = q0;
            s_sum[r0 + 8][wc] = s1; s_sq[r0 + 8][wc] = q1;
        }
    }
    __syncthreads();
    if (t < 128) {
        float s = s_sum[t][0] + s_sum[t][1] + s_sum[t][2] + s_sum[t][3];
        float q = s_sq[t][0] + s_sq[t][1] + s_sq[t][2] + s_sq[t][3];
        float mu = s * (1.0f / 256.0f);
        s_mu[t] = mu;
        s_inv[t] = rsqrtf(fmaxf(q * (1.0f / 256.0f) - mu * mu, 0.f) + 1e-5f);
    }
    __syncthreads();
    {
        float m0[8], m1[8];
#pragma unroll
        for (int nt = 0; nt < 8; nt++) { m0[nt] = -INFINITY; m1[nt] = -INFINITY; }
#pragma unroll
        for (int tile = 0; tile < 2; tile++) {
            int r0 = wr * 32 + tile * 16 + gid;
            float mu0 = s_mu[r0], inv0 = s_inv[r0], mu1 = s_mu[r0 + 8], inv1 = s_inv[r0 + 8];
#pragma unroll
            for (int nt = 0; nt < 8; nt++) {
                int c0 = wc * 64 + nt * 8 + 2 * tid4;
                float gg0 = s_g[c0], gg1 = s_g[c0 + 1], bb0 = s_be[c0], bb1 = s_be[c0 + 1];
                float4 c = acc[tile][nt];
                float y00 = (c.x - mu0) * inv0 * gg0 + bb0;
                float y01 = (c.y - mu0) * inv0 * gg1 + bb1;
                float y10 = (c.z - mu1) * inv1 * gg0 + bb0;
                float y11 = (c.w - mu1) * inv1 * gg1 + bb1;
                m0[nt] = fmaxf(m0[nt], fmaxf(y00, y10));
                m1[nt] = fmaxf(m1[nt], fmaxf(y01, y11));
            }
        }
#pragma unroll
        for (int nt = 0; nt < 8; nt++) {
#pragma unroll
            for (int o = 4; o <= 16; o <<= 1) {
                m0[nt] = fmaxf(m0[nt], __shfl_xor_sync(FULLMASK, m0[nt], o));
                m1[nt] = fmaxf(m1[nt], __shfl_xor_sync(FULLMASK, m1[nt], o));
            }
            if (gid == 0) {
                int c0 = wc * 64 + nt * 8 + 2 * tid4;
                // per-M-warp-row partial; merge across wr via fkey-atomic in SMEM-free way:
                if (wr == 0) { s_cmax[0][c0] = m0[nt]; s_cmax[0][c0 + 1] = m1[nt]; }
            }
        }
        // other wr rows: merge via atomicMax on shared after first write
        __syncthreads();
#pragma unroll
        for (int nt = 0; nt < 8; nt++) {
            if (gid == 0 && wr != 0) {
                int c0 = wc * 64 + nt * 8 + 2 * tid4;
                s_cmax[wr][c0] = m0[nt];
                s_cmax[wr][c0 + 1] = m1[nt];
            }
        }
    }
    __syncthreads();
    if (t < 256) {
        float mm = fmaxf(fmaxf(s_cmax[0][t], s_cmax[1][t]), fmaxf(s_cmax[2][t], s_cmax[3][t]));
        atomicMax(&g_pooled[(bB << 8) + t], fkey(mm));
    }
}

// ==================== final 4-row MLP (k-sliced, 4 tiny kernels) =============
__device__ __forceinline__ float bsum256(float v, float* sred) {
#pragma unroll
    for (int o = 16; o; o >>= 1) v += __shfl_xor_sync(FULLMASK, v, o);
    if ((threadIdx.x & 31) == 0) sred[threadIdx.x >> 5] = v;
    __syncthreads();
    float s = 0.f;
#pragma unroll
    for (int w = 0; w < 8; w++) s += sred[w];
    __syncthreads();
    return s;
}

__global__ __launch_bounds__(256) void k_fg(const float* __restrict__ w, int stage) {
    __shared__ float xin[4][256];
    int j = blockIdx.x, t = threadIdx.x;
    if (stage == 0)
        for (int i = t; i < 1024; i += 256) ((float*)xin)[i] = funkey(g_pooled[i]);
    else
        for (int i = t; i < 1024; i += 256) ((float*)xin)[i] = g_ft[i];
    __syncthreads();
    float a0 = 0.f, a1 = 0.f, a2 = 0.f, a3 = 0.f;
#pragma unroll
    for (int kk = 0; kk < 16; kk++) {
        float wv = __ldg(&w[(j * 16 + kk) * 256 + t]);
        a0 = fmaf(xin[0][j * 16 + kk], wv, a0);
        a1 = fmaf(xin[1][j * 16 + kk], wv, a1);
        a2 = fmaf(xin[2][j * 16 + kk], wv, a2);
        a3 = fmaf(xin[3][j * 16 + kk], wv, a3);
    }
    float* dst = stage ? g_fp2 : g_fp1;
    dst[(j * 4 + 0) * 256 + t] = a0;
    dst[(j * 4 + 1) * 256 + t] = a1;
    dst[(j * 4 + 2) * 256 + t] = a2;
    dst[(j * 4 + 3) * 256 + t] = a3;
}

__global__ __launch_bounds__(256) void k_fr(const float* __restrict__ bias,
                                            const float* __restrict__ gam,
                                            const float* __restrict__ bet,
                                            int stage, float* __restrict__ out) {
    __shared__ float sred[8];
    int t = threadIdx.x;
    const float* src = stage ? g_fp2 : g_fp1;
    for (int b = 0; b < 4; b++) {
        float y = bias[t];
#pragma unroll
        for (int j = 0; j < 16; j++) y += src[(j * 4 + b) * 256 + t];
        float mu = bsum256(y, sred) * (1.0f / 256.0f);
        float d = y - mu;
        float var = bsum256(d * d, sred) * (1.0f / 256.0f);
        float z = d * rsqrtf(var + 1e-5f) * gam[t] + bet[t];
        if (stage == 0) g_ft[b * 256 + t] = gelu_exact(z);
        else out[b * 256 + t] = z;
    }
}

// ==================== launcher ===============================================
extern "C" void kernel_launch(void* const* d_in, const int* in_sizes, int n_in,
                              void* d_out, int out_size) {
    const float* xyz  = (const float*)d_in[0];
    const float* pf   = (const float*)d_in[1];
    const float* w1   = (const float*)d_in[2];
    const float* b1   = (const float*)d_in[3];
    const float* g1   = (const float*)d_in[4];
    const float* be1  = (const float*)d_in[5];
    const float* w2   = (const float*)d_in[6];
    const float* b2   = (const float*)d_in[7];
    const float* g2   = (const float*)d_in[8];
    const float* be2  = (const float*)d_in[9];
    const float* pw1  = (const float*)d_in[10];
    const float* pb1  = (const float*)d_in[11];
    const float* pg1  = (const float*)d_in[12];
    const float* pbe1 = (const float*)d_in[13];
    const float* pw2  = (const float*)d_in[14];
    const float* pb2  = (const float*)d_in[15];
    const float* pg2  = (const float*)d_in[16];
    const float* pbe2 = (const float*)d_in[17];
    float* out = (float*)d_out;

    static int attr_done = 0;
    if (!attr_done) {
        cudaFuncSetAttribute(k_mlp, cudaFuncAttributeMaxDynamicSharedMemorySize, SMEM_DYN);
        attr_done = 1;
    }

    k_init<<<4, 256>>>();
    k_prep<<<224, 256>>>(w1, w2);
    k_ball<<<dim3(512, 4), 256>>>(xyz);
    k_mlp<<<4096, 512, SMEM_DYN>>>(xyz, pf, b1, g1, be1, b2, g2, be2);
    k_fg<<<16, 256>>>(pw1, 0);
    k_fr<<<1, 256>>>(pb1, pg1, pbe1, 0, out);
    k_fg<<<16, 256>>>(pw2, 1);
    k_fr<<<1, 256>>>(pb2, pg2, pbe2, 1, out);
}